// round 11
// baseline (speedup 1.0000x reference)
#include <cuda_runtime.h>
#include <cuda_bf16.h>
#include <math.h>
#include <stdint.h>

#define BB 32
#define NN 512
#define DD 512
#define DEG 8
#define EE (BB*NN*DEG)   // 131072
#define DHD 64
#define H2C 4
#define MT (BB*NN)       // 16384

// ---- fp32 scratch for attention ----
__device__ float g_q[MT*DD];
__device__ float g_k[MT*DD];
__device__ float g_v[MT*DD];
__device__ float g_ef[EE*H2C*DHD];

// ---- activation bf16 hi/lo planes ----
__device__ __nv_bfloat16 g_xq_h[MT*DD], g_xq_l[MT*DD];
__device__ __nv_bfloat16 g_xk_h[MT*DD], g_xk_l[MT*DD];
__device__ __nv_bfloat16 g_xv_h[MT*DD], g_xv_l[MT*DD];
__device__ __nv_bfloat16 g_eg_h[(size_t)EE*DD], g_eg_l[(size_t)EE*DD];
__device__ __nv_bfloat16 g_hb_h[(size_t)EE*DD], g_hb_l[(size_t)EE*DD];
__device__ __nv_bfloat16 g_cx_h[MT*DD], g_cx_l[MT*DD];
__device__ __nv_bfloat16 g_ou_h[MT*DD], g_ou_l[MT*DD];

// ---- transposed weight planes: [N][K] bf16, hi plane then lo plane ----
#define WT_TOT 2228224
__device__ __nv_bfloat16 g_wt[2*WT_TOT];

__device__ __forceinline__ float sspf(float x) {
    float sp = (x > 15.f) ? x : log1pf(expf(x));
    return sp - 0.69314718055994531f;
}

__device__ __forceinline__ void cp16s(uint32_t dst, const void* src) {
    asm volatile("cp.async.cg.shared.global [%0], [%1], 16;\n" :: "r"(dst), "l"(src));
}
__device__ __forceinline__ void cp_commit() {
    asm volatile("cp.async.commit_group;\n");
}

// split fp32 pair -> packed bf16 hi + packed bf16 residual lo (x0 in low 16)
__device__ __forceinline__ void split2(float x0, float x1, unsigned &hi, unsigned &lo) {
    asm("cvt.rn.bf16x2.f32 %0, %1, %2;" : "=r"(hi) : "f"(x1), "f"(x0));
    float h0 = __uint_as_float(hi << 16);
    float h1 = __uint_as_float(hi & 0xffff0000u);
    float l0 = x0 - h0;
    float l1 = x1 - h1;
    asm("cvt.rn.bf16x2.f32 %0, %1, %2;" : "=r"(lo) : "f"(l1), "f"(l0));
}

__device__ __forceinline__ void mma_bf16(float* c, const unsigned* a, unsigned b0, unsigned b1) {
    asm volatile(
        "mma.sync.aligned.m16n8k16.row.col.f32.bf16.bf16.f32 "
        "{%0,%1,%2,%3}, {%4,%5,%6,%7}, {%8,%9}, {%0,%1,%2,%3};\n"
        : "+f"(c[0]), "+f"(c[1]), "+f"(c[2]), "+f"(c[3])
        : "r"(a[0]), "r"(a[1]), "r"(a[2]), "r"(a[3]), "r"(b0), "r"(b1));
}

__device__ __forceinline__ void ldsm4(unsigned* r, uint32_t addr) {
    asm volatile("ldmatrix.sync.aligned.m8n8.x4.shared.b16 {%0,%1,%2,%3}, [%4];"
                 : "=r"(r[0]), "=r"(r[1]), "=r"(r[2]), "=r"(r[3]) : "r"(addr));
}

// ================= ldmatrix-based split-precision bf16 GEMM =================
// C = act((A @ W + bias) * scale).  A planes [M][K] bf16 hi/lo; B = W^T planes [N][K].
// AMODE==1: A rows gathered (K=1024): cols 0..511 from row (bi,ii), 512.. from (bi,jj).
// WMODE: 0 = fp32 C; 1 = bf16 hi/lo planes; 2 = both.
// BM=128 BN=128 BK=32; 8 warps: warp tile 32(m) x 64(n); smem pitch 80B (conflict-free LDSM).
#define BM 128
#define BN 128
#define GK 32
#define PITCHB 80u          // bytes per smem row (40 bf16)
#define PLANEB 10240u       // 128 rows * 80B
#define STGB   40960u       // 4 planes per stage
#define SMEM_BYTES (2*STGB) // 81920

template<int AMODE, int ACT, int WMODE>
__global__ __launch_bounds__(256, 2)
void gemm_ls(const __nv_bfloat16* __restrict__ Ah, const __nv_bfloat16* __restrict__ Al,
             const __nv_bfloat16* __restrict__ Bh, const __nv_bfloat16* __restrict__ Bl,
             const float* __restrict__ bias,
             float* __restrict__ C, __nv_bfloat16* __restrict__ Ch, __nv_bfloat16* __restrict__ Cl,
             int M, int N, int K, float scale, const int* __restrict__ pair)
{
    extern __shared__ __nv_bfloat16 sm[];
    const uint32_t sbase = (uint32_t)__cvta_generic_to_shared(sm);

    const int tid  = threadIdx.x;
    const int warp = tid >> 5;
    const int lane = tid & 31;
    const int g    = lane >> 2;
    const int cq   = lane & 3;
    const int wm   = (warp & 3) * 32;
    const int wn   = (warp >> 2) * 64;
    const int m0   = blockIdx.x * BM;
    const int n0   = blockIdx.y * BN;

    // gather rows (AMODE==1): this thread loads A rows (tid>>3)+32l
    int rA[4], rB[4];
    if (AMODE == 1) {
        #pragma unroll
        for (int l = 0; l < 4; l++) {
            int ar = (tid >> 3) + 32 * l;
            int e  = m0 + ar;
            int bi = pair[e];
            rA[l] = bi * NN + pair[EE + e];
            rB[l] = bi * NN + pair[2 * EE + e];
        }
    }

    float acc[2][8][4];
    #pragma unroll
    for (int i = 0; i < 2; i++)
        #pragma unroll
        for (int j = 0; j < 8; j++)
            #pragma unroll
            for (int t = 0; t < 4; t++) acc[i][j][t] = 0.f;

    auto load_stage = [&](int it) {
        const int k0 = it * GK;
        const uint32_t sb = sbase + (unsigned)(it & 1) * STGB;
        #pragma unroll
        for (int l = 0; l < 4; l++) {
            int idx = tid + l * 256;
            int r   = idx >> 3;
            int sub = idx & 7;
            int pl  = sub >> 2;          // 0=hi 1=lo
            int c   = (sub & 3) * 8;     // bf16 col within BK
            // A
            const __nv_bfloat16* sa;
            if (AMODE == 0) {
                sa = (pl ? Al : Ah) + (size_t)(m0 + r) * K + k0 + c;
            } else {
                int row = (k0 < 512) ? rA[l] : rB[l];
                sa = (pl ? Al : Ah) + (size_t)row * DD + (k0 & 511) + c;
            }
            cp16s(sb + (unsigned)pl * PLANEB + (unsigned)r * PITCHB + (unsigned)c * 2u, sa);
            // B (n-major [N][K])
            const __nv_bfloat16* sbp = (pl ? Bl : Bh) + (size_t)(n0 + r) * K + k0 + c;
            cp16s(sb + 2u * PLANEB + (unsigned)pl * PLANEB + (unsigned)r * PITCHB + (unsigned)c * 2u, sbp);
        }
        cp_commit();
    };

    const int nIt = K / GK;
    load_stage(0);

    for (int it = 0; it < nIt; it++) {
        if (it + 1 < nIt) {
            load_stage(it + 1);
            asm volatile("cp.async.wait_group 1;\n");
        } else {
            asm volatile("cp.async.wait_group 0;\n");
        }
        __syncthreads();

        const uint32_t sb = sbase + (unsigned)(it & 1) * STGB;
        const uint32_t lrow = (unsigned)(lane & 15) * PITCHB;
        #pragma unroll
        for (int kk = 0; kk < 2; kk++) {
            const uint32_t kc = (unsigned)(kk * 16 + (lane >> 4) * 8) * 2u;
            unsigned ah[2][4], al2[2][4];
            #pragma unroll
            for (int i = 0; i < 2; i++) {
                uint32_t ra = sb + (unsigned)(wm + 16 * i) * PITCHB + lrow + kc;
                ldsm4(ah[i],  ra);
                ldsm4(al2[i], ra + PLANEB);
            }
            #pragma unroll
            for (int j = 0; j < 4; j++) {
                uint32_t rb = sb + 2u * PLANEB + (unsigned)(wn + 16 * j) * PITCHB + lrow + kc;
                unsigned bh4[4], bl4[4];
                ldsm4(bh4, rb);
                ldsm4(bl4, rb + PLANEB);
                #pragma unroll
                for (int i = 0; i < 2; i++)
                    #pragma unroll
                    for (int t = 0; t < 2; t++) {
                        float* c = acc[i][2 * j + t];
                        mma_bf16(c, ah[i],  bh4[t], bh4[2 + t]);  // hi*hi
                        mma_bf16(c, ah[i],  bl4[t], bl4[2 + t]);  // hi*lo
                        mma_bf16(c, al2[i], bh4[t], bh4[2 + t]);  // lo*hi
                    }
            }
        }
        __syncthreads();
    }

    // epilogue: c0:(g,2cq) c1:(g,2cq+1) c2:(g+8,2cq) c3:(g+8,2cq+1)
    #pragma unroll
    for (int i = 0; i < 2; i++) {
        int mA = m0 + wm + i * 16 + g;
        #pragma unroll
        for (int j = 0; j < 8; j++) {
            int n = n0 + wn + j * 8 + 2 * cq;
            float2 bv = *reinterpret_cast<const float2*>(bias + n);
            float v0 = (acc[i][j][0] + bv.x) * scale;
            float v1 = (acc[i][j][1] + bv.y) * scale;
            float v2 = (acc[i][j][2] + bv.x) * scale;
            float v3 = (acc[i][j][3] + bv.y) * scale;
            if (ACT == 1) { v0 = sspf(v0); v1 = sspf(v1); v2 = sspf(v2); v3 = sspf(v3); }
            size_t o0 = (size_t)mA * N + n;
            size_t o1 = (size_t)(mA + 8) * N + n;
            if (WMODE == 0 || WMODE == 2) {
                *reinterpret_cast<float2*>(C + o0) = make_float2(v0, v1);
                *reinterpret_cast<float2*>(C + o1) = make_float2(v2, v3);
            }
            if (WMODE >= 1) {
                unsigned h, l;
                split2(v0, v1, h, l);
                *reinterpret_cast<unsigned*>(&Ch[o0]) = h;
                *reinterpret_cast<unsigned*>(&Cl[o0]) = l;
                split2(v2, v3, h, l);
                *reinterpret_cast<unsigned*>(&Ch[o1]) = h;
                *reinterpret_cast<unsigned*>(&Cl[o1]) = l;
            }
        }
    }
}

// ============ weight prepack: W[K][N] fp32 -> W^T planes [N][K] bf16 hi/lo ============
__global__ void prepack_wt(const float* __restrict__ W, __nv_bfloat16* __restrict__ th,
                           __nv_bfloat16* __restrict__ tl, int K, int N)
{
    int idx = blockIdx.x * blockDim.x + threadIdx.x;
    if (idx >= N * K) return;
    int n = idx / K, k = idx - n * K;
    float x = W[(size_t)k * N + n];
    __nv_bfloat16 h = __float2bfloat16(x);
    th[idx] = h;
    tl[idx] = __float2bfloat16(x - __bfloat162float(h));
}

// ============ activation split: X fp32 -> bf16 hi/lo planes ============
__global__ void conv_split(const float* __restrict__ X, __nv_bfloat16* __restrict__ Xh,
                           __nv_bfloat16* __restrict__ Xl, int n4)
{
    int idx = blockIdx.x * blockDim.x + threadIdx.x;
    if (idx >= n4) return;
    float4 v = reinterpret_cast<const float4*>(X)[idx];
    unsigned h01, l01, h23, l23;
    split2(v.x, v.y, h01, l01);
    split2(v.z, v.w, h23, l23);
    reinterpret_cast<uint2*>(Xh)[idx] = make_uint2(h01, h23);
    reinterpret_cast<uint2*>(Xl)[idx] = make_uint2(l01, l23);
}

// ================= local (edge) attention =================
__global__ void local_attn_k(const int* __restrict__ pair)
{
    int w    = (blockIdx.x * blockDim.x + threadIdx.x) >> 5;
    int lane = threadIdx.x & 31;
    int hl   = w & 3;
    int bi_i = w >> 2;
    int b    = bi_i >> 9;
    int h    = 4 + hl;
    size_t qoff = (size_t)bi_i * DD + h * DHD + lane * 2;
    float2 qv = *reinterpret_cast<const float2*>(&g_q[qoff]);
    int e0 = bi_i * DEG;

    float s[DEG];
    int   js[DEG];
    #pragma unroll
    for (int d = 0; d < DEG; d++) {
        int e = e0 + d;
        int j = pair[2 * EE + e];
        js[d] = j;
        float2 kv  = *reinterpret_cast<const float2*>(&g_k[((size_t)(b * NN + j)) * DD + h * DHD + lane * 2]);
        float2 efv = *reinterpret_cast<const float2*>(&g_ef[(size_t)e * (H2C * DHD) + hl * DHD + lane * 2]);
        float p = qv.x * kv.x * efv.x + qv.y * kv.y * efv.y;
        #pragma unroll
        for (int off = 16; off > 0; off >>= 1) p += __shfl_xor_sync(0xffffffffu, p, off);
        s[d] = p;
    }
    float m = s[0];
    #pragma unroll
    for (int d = 1; d < DEG; d++) m = fmaxf(m, s[d]);
    float sum = 0.f;
    #pragma unroll
    for (int d = 0; d < DEG; d++) { s[d] = expf(s[d] - m); sum += s[d]; }
    float inv = 1.f / sum;
    float2 accv = make_float2(0.f, 0.f);
    #pragma unroll
    for (int d = 0; d < DEG; d++) {
        float wgt = s[d] * inv;
        float2 vv = *reinterpret_cast<const float2*>(&g_v[((size_t)(b * NN + js[d])) * DD + h * DHD + lane * 2]);
        accv.x = fmaf(wgt, vv.x, accv.x);
        accv.y = fmaf(wgt, vv.y, accv.y);
    }
    size_t cidx = (size_t)bi_i * DD + hl * 128 + 64 + lane * 2;
    unsigned hh, ll;
    split2(accv.x, accv.y, hh, ll);
    *reinterpret_cast<unsigned*>(&g_cx_h[cidx]) = hh;
    *reinterpret_cast<unsigned*>(&g_cx_l[cidx]) = ll;
}

// ================= global attention =================
__global__ void global_attn_k(float* __restrict__ top)
{
    int id = blockIdx.x;
    int i  = id & 511;
    int bh = id >> 9;
    int h  = bh & 3;
    int b  = bh >> 2;
    int t  = threadIdx.x;

    __shared__ float qs[64];
    __shared__ float sc[512];
    __shared__ float red[128];

    size_t rowoff = ((size_t)(b * NN + i)) * DD + h * DHD;
    if (t < 64) qs[t] = g_q[rowoff + t];
    __syncthreads();

    float svals[4];
    float lmax = -1e30f;
    #pragma unroll
    for (int r = 0; r < 4; r++) {
        int j = t + r * 128;
        const float4* kp = reinterpret_cast<const float4*>(&g_k[((size_t)(b * NN + j)) * DD + h * DHD]);
        float s = 0.f;
        #pragma unroll
        for (int d4 = 0; d4 < 16; d4++) {
            float4 kk = kp[d4];
            s += qs[d4 * 4 + 0] * kk.x + qs[d4 * 4 + 1] * kk.y
               + qs[d4 * 4 + 2] * kk.z + qs[d4 * 4 + 3] * kk.w;
        }
        svals[r] = s;
        if (h == 0) top[((size_t)(b * NN + i)) * NN + j] = s;
        lmax = fmaxf(lmax, s);
    }
    red[t] = lmax; __syncthreads();
    #pragma unroll
    for (int off = 64; off > 0; off >>= 1) {
        if (t < off) red[t] = fmaxf(red[t], red[t + off]);
        __syncthreads();
    }
    float mx = red[0];
    __syncthreads();
    float lsum = 0.f;
    #pragma unroll
    for (int r = 0; r < 4; r++) {
        float p = expf(svals[r] - mx);
        sc[t + r * 128] = p;
        lsum += p;
    }
    red[t] = lsum; __syncthreads();
    #pragma unroll
    for (int off = 64; off > 0; off >>= 1) {
        if (t < off) red[t] += red[t + off];
        __syncthreads();
    }
    float inv = 1.f / red[0];
    __syncthreads();
    int d    = t & 63;
    int half = t >> 6;
    const float* vp = &g_v[((size_t)(b * NN + half * 256)) * DD + h * DHD + d];
    float acc = 0.f;
    #pragma unroll 8
    for (int j = 0; j < 256; j++) acc = fmaf(sc[half * 256 + j], vp[(size_t)j * DD], acc);
    red[t] = acc; __syncthreads();
    if (t < 64) {
        float val = (red[t] + red[t + 64]) * inv;
        size_t cidx = (size_t)(b * NN + i) * DD + h * 128 + t;
        __nv_bfloat16 hb = __float2bfloat16(val);
        g_cx_h[cidx] = hb;
        g_cx_l[cidx] = __float2bfloat16(val - __bfloat162float(hb));
    }
}

// ================= launch =================
extern "C" void kernel_launch(void* const* d_in, const int* in_sizes, int n_in,
                              void* d_out, int out_size)
{
    const float* key   = (const float*)d_in[0];
    const float* value = (const float*)d_in[1];
    const float* query = (const float*)d_in[2];
    const float* edge  = (const float*)d_in[4];
    const int*   pair  = (const int*)d_in[5];
    const float* Wq = (const float*)d_in[6];  const float* bq = (const float*)d_in[7];
    const float* Wk = (const float*)d_in[8];  const float* bk = (const float*)d_in[9];
    const float* Wv = (const float*)d_in[10]; const float* bv = (const float*)d_in[11];
    const float* Wo = (const float*)d_in[12]; const float* bo = (const float*)d_in[13];
    const float* ep_w1 = (const float*)d_in[14]; const float* ep_b1 = (const float*)d_in[15];
    const float* ep_w2 = (const float*)d_in[16]; const float* ep_b2 = (const float*)d_in[17];
    const float* eu_w1 = (const float*)d_in[18]; const float* eu_b1 = (const float*)d_in[19];
    const float* eu_w2 = (const float*)d_in[20]; const float* eu_b2 = (const float*)d_in[21];

    float* out  = (float*)d_out;
    float* top  = out + (size_t)MT * DD;
    float* eupd = top + (size_t)BB * NN * NN;

    float *q, *k, *v, *ef;
    cudaGetSymbolAddress((void**)&q,  g_q);
    cudaGetSymbolAddress((void**)&k,  g_k);
    cudaGetSymbolAddress((void**)&v,  g_v);
    cudaGetSymbolAddress((void**)&ef, g_ef);
    __nv_bfloat16 *xqh,*xql,*xkh,*xkl,*xvh,*xvl,*egh,*egl,*hbh,*hbl,*cxh,*cxl,*ouh,*oul,*wt;
    cudaGetSymbolAddress((void**)&xqh, g_xq_h); cudaGetSymbolAddress((void**)&xql, g_xq_l);
    cudaGetSymbolAddress((void**)&xkh, g_xk_h); cudaGetSymbolAddress((void**)&xkl, g_xk_l);
    cudaGetSymbolAddress((void**)&xvh, g_xv_h); cudaGetSymbolAddress((void**)&xvl, g_xv_l);
    cudaGetSymbolAddress((void**)&egh, g_eg_h); cudaGetSymbolAddress((void**)&egl, g_eg_l);
    cudaGetSymbolAddress((void**)&hbh, g_hb_h); cudaGetSymbolAddress((void**)&hbl, g_hb_l);
    cudaGetSymbolAddress((void**)&cxh, g_cx_h); cudaGetSymbolAddress((void**)&cxl, g_cx_l);
    cudaGetSymbolAddress((void**)&ouh, g_ou_h); cudaGetSymbolAddress((void**)&oul, g_ou_l);
    cudaGetSymbolAddress((void**)&wt,  g_wt);

    // arena offsets (bf16 elems) for hi planes; lo plane = +WT_TOT
    const size_t offWq = 0,       offWk = 262144, offWv = 524288, offWo = 786432;
    const size_t offE1 = 1048576, offE2 = 1310720, offU1 = 1441792, offU2 = 1966080;

    cudaFuncSetAttribute(gemm_ls<0,0,0>, cudaFuncAttributeMaxDynamicSharedMemorySize, SMEM_BYTES);
    cudaFuncSetAttribute(gemm_ls<0,1,1>, cudaFuncAttributeMaxDynamicSharedMemorySize, SMEM_BYTES);
    cudaFuncSetAttribute(gemm_ls<0,0,2>, cudaFuncAttributeMaxDynamicSharedMemorySize, SMEM_BYTES);
    cudaFuncSetAttribute(gemm_ls<1,1,1>, cudaFuncAttributeMaxDynamicSharedMemorySize, SMEM_BYTES);

    // ---- prepack transposed weight planes ----
    prepack_wt<<<(262144+255)/256, 256>>>(Wq,    wt+offWq, wt+offWq+WT_TOT, 512, 512);
    prepack_wt<<<(262144+255)/256, 256>>>(Wk,    wt+offWk, wt+offWk+WT_TOT, 512, 512);
    prepack_wt<<<(262144+255)/256, 256>>>(Wv,    wt+offWv, wt+offWv+WT_TOT, 512, 512);
    prepack_wt<<<(262144+255)/256, 256>>>(Wo,    wt+offWo, wt+offWo+WT_TOT, 512, 512);
    prepack_wt<<<(262144+255)/256, 256>>>(ep_w1, wt+offE1, wt+offE1+WT_TOT, 512, 512);
    prepack_wt<<<(131072+255)/256, 256>>>(ep_w2, wt+offE2, wt+offE2+WT_TOT, 512, 256);
    prepack_wt<<<(524288+255)/256, 256>>>(eu_w1, wt+offU1, wt+offU1+WT_TOT, 1024, 512);
    prepack_wt<<<(262144+255)/256, 256>>>(eu_w2, wt+offU2, wt+offU2+WT_TOT, 512, 512);

    // ---- split input activations ----
    conv_split<<<(MT*DD/4 + 255)/256, 256>>>(query, xqh, xql, MT*DD/4);
    conv_split<<<(MT*DD/4 + 255)/256, 256>>>(key,   xkh, xkl, MT*DD/4);
    conv_split<<<(MT*DD/4 + 255)/256, 256>>>(value, xvh, xvl, MT*DD/4);
    conv_split<<<(EE*DD/4 + 255)/256, 256>>>(edge,  egh, egl, EE*DD/4);

    dim3 blk(256);
    // QKV projections (q pre-scaled by 1/sqrt(DH)=0.125)
    gemm_ls<0,0,0><<<dim3(MT/BM, 512/BN), blk, SMEM_BYTES>>>(xqh, xql, wt+offWq, wt+offWq+WT_TOT, bq, q, nullptr, nullptr, MT, 512, 512, 0.125f, nullptr);
    gemm_ls<0,0,0><<<dim3(MT/BM, 512/BN), blk, SMEM_BYTES>>>(xkh, xkl, wt+offWk, wt+offWk+WT_TOT, bk, k, nullptr, nullptr, MT, 512, 512, 1.0f, nullptr);
    gemm_ls<0,0,0><<<dim3(MT/BM, 512/BN), blk, SMEM_BYTES>>>(xvh, xvl, wt+offWv, wt+offWv+WT_TOT, bv, v, nullptr, nullptr, MT, 512, 512, 1.0f, nullptr);
    // edge-feature MLP
    gemm_ls<0,1,1><<<dim3(EE/BM, 512/BN), blk, SMEM_BYTES>>>(egh, egl, wt+offE1, wt+offE1+WT_TOT, ep_b1, nullptr, hbh, hbl, EE, 512, 512, 1.0f, nullptr);
    gemm_ls<0,0,0><<<dim3(EE/BM, 256/BN), blk, SMEM_BYTES>>>(hbh, hbl, wt+offE2, wt+offE2+WT_TOT, ep_b2, ef, nullptr, nullptr, EE, 256, 512, 1.0f, nullptr);
    // attention -> ctx planes (+ top_score)
    local_attn_k<<<(MT*H2C)/8, 256>>>(pair);
    global_attn_k<<<BB*H2C*NN, 128>>>(top);
    // output projection -> out fp32 + out planes
    gemm_ls<0,0,2><<<dim3(MT/BM, 512/BN), blk, SMEM_BYTES>>>(cxh, cxl, wt+offWo, wt+offWo+WT_TOT, bo, out, ouh, oul, MT, 512, 512, 1.0f, nullptr);
    // edge update MLP (gather concat rows, K=1024)
    gemm_ls<1,1,1><<<dim3(EE/BM, 512/BN), blk, SMEM_BYTES>>>(ouh, oul, wt+offU1, wt+offU1+WT_TOT, eu_b1, nullptr, hbh, hbl, EE, 512, 1024, 1.0f, pair);
    gemm_ls<0,0,0><<<dim3(EE/BM, 512/BN), blk, SMEM_BYTES>>>(hbh, hbl, wt+offU2, wt+offU2+WT_TOT, eu_b2, eupd, nullptr, nullptr, EE, 512, 512, 1.0f, nullptr);
}